// round 8
// baseline (speedup 1.0000x reference)
#include <cuda_runtime.h>
#include <cstdint>

#define C_NUM 100000
#define D_NUM 256
#define B_NUM 1024
#define EPSV 1e-12f
#define COPY_CTAS_Y 16           // first 16 y-slots * 8 x = 128 copy CTAs
#define GEMM_TILES_Y 782

__device__ float g_xnorm[B_NUM * D_NUM];   // tf32-rounded normalized x
__device__ float g_xexact[B_NUM * D_NUM];  // exact normalized x
__device__ int   g_next[B_NUM];
__device__ int   g_head[B_NUM];

__device__ __forceinline__ uint32_t smem_u32(const void* p) {
    uint32_t a;
    asm("{ .reg .u64 t; cvta.to.shared.u64 t, %1; cvt.u32.u64 %0, t; }" : "=r"(a) : "l"(p));
    return a;
}
__device__ __forceinline__ unsigned f2tf(float f) {
    unsigned u;
    asm("cvt.rna.tf32.f32 %0, %1;" : "=r"(u) : "f"(f));
    return u;
}
__device__ __forceinline__ void cp16(uint32_t daddr, const void* gptr) {
    asm volatile("cp.async.cg.shared.global [%0], [%1], 16;" :: "r"(daddr), "l"(gptr) : "memory");
}
#define CP_COMMIT() asm volatile("cp.async.commit_group;" ::: "memory")

__device__ __forceinline__ void ldsm4(unsigned r[4], uint32_t addr) {
    asm volatile("ldmatrix.sync.aligned.m8n8.x4.shared.b16 {%0,%1,%2,%3}, [%4];"
                 : "=r"(r[0]), "=r"(r[1]), "=r"(r[2]), "=r"(r[3]) : "r"(addr));
}
__device__ __forceinline__ void mma_tf32(float d[4], const unsigned a[4], const unsigned b[2]) {
    asm volatile(
        "mma.sync.aligned.m16n8k8.row.col.f32.tf32.tf32.f32 "
        "{%0,%1,%2,%3}, {%4,%5,%6,%7}, {%8,%9}, {%0,%1,%2,%3};\n"
        : "+f"(d[0]), "+f"(d[1]), "+f"(d[2]), "+f"(d[3])
        : "r"(a[0]), "r"(a[1]), "r"(a[2]), "r"(a[3]),
          "r"(b[0]), "r"(b[1]));
}
__device__ __forceinline__ uint32_t sw128(uint32_t off) { return off ^ ((off >> 3) & 0x70); }

// ---------------------------------------------------------------------------
// K_PREP: fused  [blocks 0..1023]=xnorm  [1024]=chain
// ---------------------------------------------------------------------------
__global__ void k_prep(const float* __restrict__ x, const int* __restrict__ tgt,
                       float* __restrict__ out_t) {
    const int by = blockIdx.x;
    const int t = threadIdx.x;
    __shared__ float ws[8];
    __shared__ int st[B_NUM];

    if (by < B_NUM) {                    // ---- xnorm row `by` ----
        float v = x[by * D_NUM + t];
        float ss = v * v;
        #pragma unroll
        for (int o = 16; o; o >>= 1) ss += __shfl_xor_sync(0xffffffffu, ss, o);
        if ((t & 31) == 0) ws[t >> 5] = ss;
        __syncthreads();
        float tot = 0.f;
        #pragma unroll
        for (int i = 0; i < 8; ++i) tot += ws[i];
        float inv = 1.f / fmaxf(sqrtf(tot), EPSV);
        float xn = v * inv;
        g_xexact[by * D_NUM + t] = xn;
        g_xnorm[by * D_NUM + t] = __uint_as_float(f2tf(xn));
        if (t == 0) out_t[by] = (float)tgt[by];
    } else {                             // ---- per-class occurrence chains ----
        #pragma unroll
        for (int k = 0; k < 4; ++k) {
            int i = t + k * 256;
            st[i] = tgt[i];
            g_next[i] = -1;
        }
        __syncthreads();
        #pragma unroll
        for (int k = 0; k < 4; ++k) {
            int i = t + k * 256;
            int me = st[i], prev = -1;
            for (int j = i - 1; j >= 0; --j)
                if (st[j] == me) { prev = j; break; }
            g_head[i] = (prev < 0) ? 1 : 0;
            if (prev >= 0) g_next[prev] = i;
        }
    }
}

// ---------------------------------------------------------------------------
// K4: TF32 mma.sync GEMM. 128x128 CTA tile, 8 warps @ 64x32, BK=32,
//     3-stage cp.async, in-register W-row sumsq (no winv kernel),
//     leading copy CTAs overlap the W->new_weight copy.
// ---------------------------------------------------------------------------
#define NSTG 3
#define STG_BYTES 32768            // A(16KB) + B(16KB) per stage
#define OFF_TILE 1024
#define SMEM_BYTES (OFF_TILE + NSTG * STG_BYTES)

__global__ __launch_bounds__(256, 2)
void k_gemm(const float* __restrict__ W, float* __restrict__ out,
            float4* __restrict__ nw4) {
    const int tid = threadIdx.x;

    // ---- leading copy CTAs: W -> new_weight output region (overlaps GEMM) ----
    if (blockIdx.y < COPY_CTAS_Y) {
        const float4* src = (const float4*)W;
        const size_t n4 = (size_t)C_NUM * 64;
        const size_t nthr = (size_t)COPY_CTAS_Y * 8 * 256;   // 32768
        size_t base = (size_t)(blockIdx.y * 8 + blockIdx.x) * 256 + tid;
        size_t i = base;
        for (; i + 3 * nthr < n4; i += 4 * nthr) {
            float4 v0 = src[i];
            float4 v1 = src[i + nthr];
            float4 v2 = src[i + 2 * nthr];
            float4 v3 = src[i + 3 * nthr];
            nw4[i] = v0; nw4[i + nthr] = v1;
            nw4[i + 2 * nthr] = v2; nw4[i + 3 * nthr] = v3;
        }
        for (; i < n4; i += nthr) nw4[i] = src[i];
        return;
    }

    extern __shared__ char smem[];
    const uint32_t sb = smem_u32(smem);
    const int lane = tid & 31, warp = tid >> 5;
    const int b0 = blockIdx.x * 128;                    // batch tile
    const int c0 = (blockIdx.y - COPY_CTAS_Y) * 128;    // class tile
    const int wm = (warp & 1) * 64;
    const int wn = (warp >> 1) * 32;

    float* winv_s = (float*)smem;      // [128] = 30/||W_row|| (filled in epilogue)

    const char* Abase = (const char*)g_xnorm + (size_t)b0 * (D_NUM * 4);
    const char* Bbase = (const char*)W;

    auto issue_load = [&](int stage, int chunk) {
        uint32_t abuf = sb + OFF_TILE + stage * STG_BYTES;
        uint32_t bbuf = abuf + 16384;
        #pragma unroll
        for (int i = 0; i < 4; ++i) {
            int slot = tid + i * 256;          // 0..1023
            int r = slot >> 3;
            int sg = (slot & 7) * 16;
            uint32_t so = sw128((uint32_t)(r * 128 + sg));
            cp16(abuf + so, Abase + (size_t)r * 1024 + chunk * 128 + sg);
            int row = c0 + r; if (row >= C_NUM) row = C_NUM - 1;
            cp16(bbuf + so, Bbase + (size_t)row * 1024 + chunk * 128 + sg);
        }
        CP_COMMIT();
    };

    float acc[4][4][4];
    #pragma unroll
    for (int i = 0; i < 4; ++i)
        #pragma unroll
        for (int j = 0; j < 4; ++j)
            #pragma unroll
            for (int r = 0; r < 4; ++r) acc[i][j][r] = 0.f;

    // per-lane partial sum-of-squares of B rows (full k by end of mainloop)
    // ssq[jp][sub] belongs to class row  wn + jp*16 + sub*8 + (lane>>2)
    float ssq[2][2] = {{0.f, 0.f}, {0.f, 0.f}};

    uint32_t a_off[4], b_off[2];
    #pragma unroll
    for (int im = 0; im < 4; ++im)
        a_off[im] = (uint32_t)((wm + im * 16 + (lane & 15)) * 128 + ((lane >> 4) << 4));
    #pragma unroll
    for (int jp = 0; jp < 2; ++jp)
        b_off[jp] = (uint32_t)((wn + jp * 16 + ((lane >> 4) << 3) + (lane & 7)) * 128
                               + (((lane >> 3) & 1) << 4));

    issue_load(0, 0);
    issue_load(1, 1);

    #pragma unroll
    for (int c = 0; c < 8; ++c) {
        if (c < 7) asm volatile("cp.async.wait_group 1;" ::: "memory");
        else       asm volatile("cp.async.wait_group 0;" ::: "memory");
        __syncthreads();
        if (c + 2 < 8) issue_load((c + 2) % NSTG, c + 2);  // stage freed at this barrier

        const uint32_t abuf = sb + OFF_TILE + (c % NSTG) * STG_BYTES;
        const uint32_t bbuf = abuf + 16384;
        #pragma unroll
        for (int ks = 0; ks < 4; ++ks) {
            unsigned af[4][4], bf[2][4];
            #pragma unroll
            for (int im = 0; im < 4; ++im)
                ldsm4(af[im], abuf + sw128(a_off[im] + ks * 32));
            #pragma unroll
            for (int jp = 0; jp < 2; ++jp) {
                ldsm4(bf[jp], bbuf + sw128(b_off[jp] + ks * 32));
                // fragment reg r of lane l = B[wn+jp*16+(r>=2?8:0)+(l>>2)][k...]
                float q0 = __uint_as_float(bf[jp][0]);
                float q1 = __uint_as_float(bf[jp][1]);
                float q2 = __uint_as_float(bf[jp][2]);
                float q3 = __uint_as_float(bf[jp][3]);
                ssq[jp][0] = fmaf(q0, q0, fmaf(q1, q1, ssq[jp][0]));
                ssq[jp][1] = fmaf(q2, q2, fmaf(q3, q3, ssq[jp][1]));
            }
            #pragma unroll
            for (int im = 0; im < 4; ++im) {
                #pragma unroll
                for (int jp = 0; jp < 2; ++jp) {
                    mma_tf32(acc[im][jp * 2 + 0], af[im], &bf[jp][0]);
                    mma_tf32(acc[im][jp * 2 + 1], af[im], &bf[jp][2]);
                }
            }
        }
    }

    // winv from in-register sumsq: reduce over the 4 lanes sharing a row
    // (lane groups l = 4q..4q+3 hold k-phases 0..3 of row base+q)
    #pragma unroll
    for (int jp = 0; jp < 2; ++jp) {
        #pragma unroll
        for (int sub = 0; sub < 2; ++sub) {
            float s = ssq[jp][sub];
            s += __shfl_xor_sync(0xffffffffu, s, 1);
            s += __shfl_xor_sync(0xffffffffu, s, 2);
            if ((warp & 1) == 0 && (lane & 3) == 0) {
                int row = wn + jp * 16 + sub * 8 + (lane >> 2);
                winv_s[row] = 30.0f / fmaxf(sqrtf(s), EPSV);
            }
        }
    }
    __syncthreads();   // winv_s visible; all reads of last stage done before tb reuse

    // epilogue: scale by 30*winv, smem transpose, coalesced float4 stores
    float* tb = (float*)(smem + OFF_TILE);   // [128][132]
    const int g4 = lane >> 2, t4 = lane & 3;
    #pragma unroll
    for (int im = 0; im < 4; ++im) {
        int r = wm + im * 16 + g4;
        #pragma unroll
        for (int jn = 0; jn < 4; ++jn) {
            int col = wn + jn * 8 + t4 * 2;
            float s0 = winv_s[col], s1 = winv_s[col + 1];
            *(float2*)&tb[r * 132 + col] =
                make_float2(acc[im][jn][0] * s0, acc[im][jn][1] * s1);
            *(float2*)&tb[(r + 8) * 132 + col] =
                make_float2(acc[im][jn][2] * s0, acc[im][jn][3] * s1);
        }
    }
    __syncthreads();
    #pragma unroll
    for (int it = 0; it < 16; ++it) {
        int r = warp + it * 8;
        int colb = lane * 4;
        float4 val = *(const float4*)&tb[r * 132 + colb];
        int gc = c0 + colb;
        if (gc < C_NUM)
            *(float4*)&out[(size_t)(b0 + r) * C_NUM + gc] = val;
    }
}

// ---------------------------------------------------------------------------
// K_UPDATE: sequential momentum update per class chain (reads copied rows)
// ---------------------------------------------------------------------------
__global__ void k_update(const int* __restrict__ tgt, float* __restrict__ nw) {
    int b = blockIdx.x;
    if (!g_head[b]) return;
    int t = threadIdx.x;
    int y = tgt[b];
    float v = nw[(size_t)y * D_NUM + t];
    __shared__ float ws[8];
    int cur = b;
    while (cur >= 0) {
        v = 0.5f * v + 0.5f * g_xexact[cur * D_NUM + t];
        float ss = v * v;
        #pragma unroll
        for (int o = 16; o; o >>= 1) ss += __shfl_xor_sync(0xffffffffu, ss, o);
        __syncthreads();
        if ((t & 31) == 0) ws[t >> 5] = ss;
        __syncthreads();
        float tot = 0.f;
        #pragma unroll
        for (int i = 0; i < 8; ++i) tot += ws[i];
        v *= 1.f / fmaxf(sqrtf(tot), EPSV);
        cur = g_next[cur];
    }
    nw[(size_t)y * D_NUM + t] = v;
}

// ---------------------------------------------------------------------------
extern "C" void kernel_launch(void* const* d_in, const int* in_sizes, int n_in,
                              void* d_out, int out_size) {
    const float* x   = (const float*)d_in[0];
    const int*   tgt = (const int*)d_in[1];
    const float* w   = (const float*)d_in[2];
    float* out      = (float*)d_out;
    float* out_pred = out;                                  // [1024][100000]
    float* out_t    = out + (size_t)B_NUM * C_NUM;          // [1024]
    float* out_nw   = out_t + B_NUM;                        // [100000][256]

    static bool attr_set = false;
    if (!attr_set) {
        cudaFuncSetAttribute(k_gemm, cudaFuncAttributeMaxDynamicSharedMemorySize, SMEM_BYTES);
        attr_set = true;
    }

    k_prep<<<B_NUM + 1, 256>>>(x, tgt, out_t);
    k_gemm<<<dim3(8, COPY_CTAS_Y + GEMM_TILES_Y), 256, SMEM_BYTES>>>(w, out_pred, (float4*)out_nw);
    k_update<<<B_NUM, 256>>>(tgt, out_nw);
}

// round 9
// speedup vs baseline: 1.4310x; 1.4310x over previous
#include <cuda_runtime.h>
#include <cstdint>

#define C_NUM 100000
#define D_NUM 256
#define B_NUM 1024
#define EPSV 1e-12f
#define COPY_CTAS_Y 16           // first 16 y-slots * 8 x = 128 copy CTAs
#define GEMM_TILES_Y 782
#define CHAIN_BLKS 128           // 8 warps each -> 1024 warps, one per element
#define WINV_BLKS 12500          // 8 warps each -> one class row per warp

__device__ float g_xnorm[B_NUM * D_NUM];   // tf32-rounded normalized x
__device__ float g_xexact[B_NUM * D_NUM];  // exact normalized x
__device__ float g_winv[C_NUM];
__device__ int   g_next[B_NUM];
__device__ int   g_head[B_NUM];

__device__ __forceinline__ uint32_t smem_u32(const void* p) {
    uint32_t a;
    asm("{ .reg .u64 t; cvta.to.shared.u64 t, %1; cvt.u32.u64 %0, t; }" : "=r"(a) : "l"(p));
    return a;
}
__device__ __forceinline__ unsigned f2tf(float f) {
    unsigned u;
    asm("cvt.rna.tf32.f32 %0, %1;" : "=r"(u) : "f"(f));
    return u;
}
__device__ __forceinline__ void cp16(uint32_t daddr, const void* gptr) {
    asm volatile("cp.async.cg.shared.global [%0], [%1], 16;" :: "r"(daddr), "l"(gptr) : "memory");
}
#define CP_COMMIT() asm volatile("cp.async.commit_group;" ::: "memory")

__device__ __forceinline__ void ldsm4(unsigned r[4], uint32_t addr) {
    asm volatile("ldmatrix.sync.aligned.m8n8.x4.shared.b16 {%0,%1,%2,%3}, [%4];"
                 : "=r"(r[0]), "=r"(r[1]), "=r"(r[2]), "=r"(r[3]) : "r"(addr));
}
__device__ __forceinline__ void mma_tf32(float d[4], const unsigned a[4], const unsigned b[2]) {
    asm volatile(
        "mma.sync.aligned.m16n8k8.row.col.f32.tf32.tf32.f32 "
        "{%0,%1,%2,%3}, {%4,%5,%6,%7}, {%8,%9}, {%0,%1,%2,%3};\n"
        : "+f"(d[0]), "+f"(d[1]), "+f"(d[2]), "+f"(d[3])
        : "r"(a[0]), "r"(a[1]), "r"(a[2]), "r"(a[3]),
          "r"(b[0]), "r"(b[1]));
}
__device__ __forceinline__ uint32_t sw128(uint32_t off) { return off ^ ((off >> 3) & 0x70); }

// ---------------------------------------------------------------------------
// K_PREP fused grid:
//   blocks [0, 1024)                      : xnorm (one batch row each)
//   blocks [1024, 1024+128)               : chain (warp-ballot, 1 elem/warp)
//   blocks [1152, 1152+12500)             : winv  (one class row per warp)
// All three sections are independent; runtime = max, not sum.
// ---------------------------------------------------------------------------
__global__ void k_prep(const float* __restrict__ x, const int* __restrict__ tgt,
                       const float4* __restrict__ w4, float* __restrict__ out_t) {
    const int by = blockIdx.x;
    const int t = threadIdx.x;

    if (by < B_NUM) {                    // ---- xnorm row `by` ----
        __shared__ float ws[8];
        float v = x[by * D_NUM + t];
        float ss = v * v;
        #pragma unroll
        for (int o = 16; o; o >>= 1) ss += __shfl_xor_sync(0xffffffffu, ss, o);
        if ((t & 31) == 0) ws[t >> 5] = ss;
        __syncthreads();
        float tot = 0.f;
        #pragma unroll
        for (int i = 0; i < 8; ++i) tot += ws[i];
        float inv = 1.f / fmaxf(sqrtf(tot), EPSV);
        float xn = v * inv;
        g_xexact[by * D_NUM + t] = xn;
        g_xnorm[by * D_NUM + t] = __uint_as_float(f2tf(xn));
        if (t == 0) out_t[by] = (float)tgt[by];
    } else if (by < B_NUM + CHAIN_BLKS) {   // ---- chain: warp-ballot scan ----
        __shared__ int st[B_NUM];
        #pragma unroll
        for (int k = 0; k < 4; ++k) st[t + k * 256] = tgt[t + k * 256];
        __syncthreads();
        const int lane = t & 31;
        const int i = (by - B_NUM) * 8 + (t >> 5);   // 0..1023, one per warp
        const int me = st[i];
        int prev = -1;
        for (int base = i - 1 - lane; ; base -= 32) {
            int j = base;
            bool hit = (j >= 0) && (st[j] == me);
            unsigned m = __ballot_sync(0xffffffffu, hit);
            if (m) { prev = i - __ffs(m); break; }          // lowest lane = largest j
            if (base - lane <= -32 || base < lane - 31) {    // whole chunk below 0
                if (base - (31 - lane) < 0 && !m) { /* fallthrough check */ }
            }
            if (base <= lane - 31 - 1 + 0) {}                // no-op keep structure
            if (base - 31 + lane < 0 && base < 0) break;     // all lanes negative next iter guard
            if (base - 32 < -32) break;                      // next chunk entirely < 0
        }
        if (lane == 0) {
            g_head[i] = (prev < 0) ? 1 : 0;
            if (prev >= 0) g_next[prev] = i;
        }
    } else {                             // ---- winv: one class per warp ----
        int gw = (by - B_NUM - CHAIN_BLKS) * 8 + (t >> 5);
        int lane = t & 31;
        if (gw < C_NUM) {
            const float4* row = w4 + (size_t)gw * 64;
            float4 a = row[lane];
            float4 b = row[lane + 32];
            float ss = a.x*a.x + a.y*a.y + a.z*a.z + a.w*a.w
                     + b.x*b.x + b.y*b.y + b.z*b.z + b.w*b.w;
            #pragma unroll
            for (int o = 16; o; o >>= 1) ss += __shfl_xor_sync(0xffffffffu, ss, o);
            if (lane == 0) g_winv[gw] = 1.f / fmaxf(sqrtf(ss), EPSV);
        }
    }
}

// init g_next (chain warps only set next[prev] when a successor exists)
__global__ void k_init_next() {
    g_next[blockIdx.x * blockDim.x + threadIdx.x] = -1;
}

// ---------------------------------------------------------------------------
// K_GEMM: TF32 mma.sync. 128x128 CTA tile, 8 warps @ 64x32, BK=32,
//         3-stage cp.async, single barrier/iter, leading copy CTAs. (R6 core)
// ---------------------------------------------------------------------------
#define NSTG 3
#define STG_BYTES 32768            // A(16KB) + B(16KB) per stage
#define OFF_TILE 1024
#define SMEM_BYTES (OFF_TILE + NSTG * STG_BYTES)

__global__ __launch_bounds__(256, 2)
void k_gemm(const float* __restrict__ W, float* __restrict__ out,
            float4* __restrict__ nw4) {
    const int tid = threadIdx.x;

    // ---- leading copy CTAs: W -> new_weight output region (overlaps GEMM) ----
    if (blockIdx.y < COPY_CTAS_Y) {
        const float4* src = (const float4*)W;
        const size_t n4 = (size_t)C_NUM * 64;
        const size_t nthr = (size_t)COPY_CTAS_Y * 8 * 256;   // 32768
        size_t base = (size_t)(blockIdx.y * 8 + blockIdx.x) * 256 + tid;
        size_t i = base;
        for (; i + 3 * nthr < n4; i += 4 * nthr) {
            float4 v0 = src[i];
            float4 v1 = src[i + nthr];
            float4 v2 = src[i + 2 * nthr];
            float4 v3 = src[i + 3 * nthr];
            nw4[i] = v0; nw4[i + nthr] = v1;
            nw4[i + 2 * nthr] = v2; nw4[i + 3 * nthr] = v3;
        }
        for (; i < n4; i += nthr) nw4[i] = src[i];
        return;
    }

    extern __shared__ char smem[];
    const uint32_t sb = smem_u32(smem);
    const int lane = tid & 31, warp = tid >> 5;
    const int b0 = blockIdx.x * 128;                    // batch tile
    const int c0 = (blockIdx.y - COPY_CTAS_Y) * 128;    // class tile
    const int wm = (warp & 1) * 64;
    const int wn = (warp >> 1) * 32;

    float* winv_s = (float*)smem;      // [128] = 30*winv
    if (tid < 128) {
        int c = c0 + tid; if (c >= C_NUM) c = C_NUM - 1;
        winv_s[tid] = 30.0f * g_winv[c];
    }

    const char* Abase = (const char*)g_xnorm + (size_t)b0 * (D_NUM * 4);
    const char* Bbase = (const char*)W;

    auto issue_load = [&](int stage, int chunk) {
        uint32_t abuf = sb + OFF_TILE + stage * STG_BYTES;
        uint32_t bbuf = abuf + 16384;
        #pragma unroll
        for (int i = 0; i < 4; ++i) {
            int slot = tid + i * 256;          // 0..1023
            int r = slot >> 3;
            int sg = (slot & 7) * 16;
            uint32_t so = sw128((uint32_t)(r * 128 + sg));
            cp16(abuf + so, Abase + (size_t)r * 1024 + chunk * 128 + sg);
            int row = c0 + r; if (row >= C_NUM) row = C_NUM - 1;
            cp16(bbuf + so, Bbase + (size_t)row * 1024 + chunk * 128 + sg);
        }
        CP_COMMIT();
    };

    float acc[4][4][4];
    #pragma unroll
    for (int i = 0; i < 4; ++i)
        #pragma unroll
        for (int j = 0; j < 4; ++j)
            #pragma unroll
            for (int r = 0; r < 4; ++r) acc[i][j][r] = 0.f;

    uint32_t a_off[4], b_off[2];
    #pragma unroll
    for (int im = 0; im < 4; ++im)
        a_off[im] = (uint32_t)((wm + im * 16 + (lane & 15)) * 128 + ((lane >> 4) << 4));
    #pragma unroll
    for (int jp = 0; jp < 2; ++jp)
        b_off[jp] = (uint32_t)((wn + jp * 16 + ((lane >> 4) << 3) + (lane & 7)) * 128
                               + (((lane >> 3) & 1) << 4));

    issue_load(0, 0);
    issue_load(1, 1);

    #pragma unroll
    for (int c = 0; c < 8; ++c) {
        if (c < 7) asm volatile("cp.async.wait_group 1;" ::: "memory");
        else       asm volatile("cp.async.wait_group 0;" ::: "memory");
        __syncthreads();
        if (c + 2 < 8) issue_load((c + 2) % NSTG, c + 2);  // stage freed at this barrier

        const uint32_t abuf = sb + OFF_TILE + (c % NSTG) * STG_BYTES;
        const uint32_t bbuf = abuf + 16384;
        #pragma unroll
        for (int ks = 0; ks < 4; ++ks) {
            unsigned af[4][4], bf[2][4];
            #pragma unroll
            for (int im = 0; im < 4; ++im)
                ldsm4(af[im], abuf + sw128(a_off[im] + ks * 32));
            #pragma unroll
            for (int jp = 0; jp < 2; ++jp)
                ldsm4(bf[jp], bbuf + sw128(b_off[jp] + ks * 32));
            #pragma unroll
            for (int im = 0; im < 4; ++im) {
                #pragma unroll
                for (int jp = 0; jp < 2; ++jp) {
                    mma_tf32(acc[im][jp * 2 + 0], af[im], &bf[jp][0]);
                    mma_tf32(acc[im][jp * 2 + 1], af[im], &bf[jp][2]);
                }
            }
        }
    }
    __syncthreads();   // all reads of last stage done before tb reuse

    // epilogue: scale by 30*winv, smem transpose, coalesced float4 stores
    float* tb = (float*)(smem + OFF_TILE);   // [128][132]
    const int g4 = lane >> 2, t4 = lane & 3;
    #pragma unroll
    for (int im = 0; im < 4; ++im) {
        int r = wm + im * 16 + g4;
        #pragma unroll
        for (int jn = 0; jn < 4; ++jn) {
            int col = wn + jn * 8 + t4 * 2;
            float s0 = winv_s[col], s1 = winv_s[col + 1];
            *(float2*)&tb[r * 132 + col] =
                make_float2(acc[im][jn][0] * s0, acc[im][jn][1] * s1);
            *(float2*)&tb[(r + 8) * 132 + col] =
                make_float2(acc[im][jn][2] * s0, acc[im][jn][3] * s1);
        }
    }
    __syncthreads();
    #pragma unroll
    for (int it = 0; it < 16; ++it) {
        int r = warp + it * 8;
        int colb = lane * 4;
        float4 val = *(const float4*)&tb[r * 132 + colb];
        int gc = c0 + colb;
        if (gc < C_NUM)
            *(float4*)&out[(size_t)(b0 + r) * C_NUM + gc] = val;
    }
}

// ---------------------------------------------------------------------------
// K_UPDATE: sequential momentum update per class chain (reads copied rows)
// ---------------------------------------------------------------------------
__global__ void k_update(const int* __restrict__ tgt, float* __restrict__ nw) {
    int b = blockIdx.x;
    if (!g_head[b]) return;
    int t = threadIdx.x;
    int y = tgt[b];
    float v = nw[(size_t)y * D_NUM + t];
    __shared__ float ws[8];
    int cur = b;
    while (cur >= 0) {
        v = 0.5f * v + 0.5f * g_xexact[cur * D_NUM + t];
        float ss = v * v;
        #pragma unroll
        for (int o = 16; o; o >>= 1) ss += __shfl_xor_sync(0xffffffffu, ss, o);
        __syncthreads();
        if ((t & 31) == 0) ws[t >> 5] = ss;
        __syncthreads();
        float tot = 0.f;
        #pragma unroll
        for (int i = 0; i < 8; ++i) tot += ws[i];
        v *= 1.f / fmaxf(sqrtf(tot), EPSV);
        cur = g_next[cur];
    }
    nw[(size_t)y * D_NUM + t] = v;
}

// ---------------------------------------------------------------------------
extern "C" void kernel_launch(void* const* d_in, const int* in_sizes, int n_in,
                              void* d_out, int out_size) {
    const float* x   = (const float*)d_in[0];
    const int*   tgt = (const int*)d_in[1];
    const float* w   = (const float*)d_in[2];
    float* out      = (float*)d_out;
    float* out_pred = out;                                  // [1024][100000]
    float* out_t    = out + (size_t)B_NUM * C_NUM;          // [1024]
    float* out_nw   = out_t + B_NUM;                        // [100000][256]

    static bool attr_set = false;
    if (!attr_set) {
        cudaFuncSetAttribute(k_gemm, cudaFuncAttributeMaxDynamicSharedMemorySize, SMEM_BYTES);
        attr_set = true;
    }

    k_init_next<<<4, 256>>>();
    k_prep<<<B_NUM + CHAIN_BLKS + WINV_BLKS, 256>>>(x, tgt, (const float4*)w, out_t);
    k_gemm<<<dim3(8, COPY_CTAS_Y + GEMM_TILES_Y), 256, SMEM_BYTES>>>(w, out_pred, (float4*)out_nw);
    k_update<<<B_NUM, 256>>>(tgt, out_nw);
}

// round 10
// speedup vs baseline: 1.4375x; 1.0045x over previous
#include <cuda_runtime.h>
#include <cstdint>

#define C_NUM 100000
#define D_NUM 256
#define B_NUM 1024
#define EPSV 1e-12f
#define COPY_CTAS_Y 16           // first 16 y-slots * 8 x = 128 copy CTAs
#define GEMM_TILES_Y 782
#define CHAIN_BLKS 128           // 8 warps each -> 1024 warps, one per element
#define WINV_BLKS 6250           // 8 warps each, 2 rows per warp

__device__ float g_xnorm[B_NUM * D_NUM];   // tf32-rounded normalized x
__device__ float g_xexact[B_NUM * D_NUM];  // exact normalized x
__device__ float g_winv[C_NUM];
__device__ int   g_next[B_NUM];
__device__ int   g_head[B_NUM];

__device__ __forceinline__ uint32_t smem_u32(const void* p) {
    uint32_t a;
    asm("{ .reg .u64 t; cvta.to.shared.u64 t, %1; cvt.u32.u64 %0, t; }" : "=r"(a) : "l"(p));
    return a;
}
__device__ __forceinline__ unsigned f2tf(float f) {
    unsigned u;
    asm("cvt.rna.tf32.f32 %0, %1;" : "=r"(u) : "f"(f));
    return u;
}
__device__ __forceinline__ void cp16(uint32_t daddr, const void* gptr) {
    asm volatile("cp.async.cg.shared.global [%0], [%1], 16;" :: "r"(daddr), "l"(gptr) : "memory");
}
#define CP_COMMIT() asm volatile("cp.async.commit_group;" ::: "memory")

__device__ __forceinline__ void ldsm4(unsigned r[4], uint32_t addr) {
    asm volatile("ldmatrix.sync.aligned.m8n8.x4.shared.b16 {%0,%1,%2,%3}, [%4];"
                 : "=r"(r[0]), "=r"(r[1]), "=r"(r[2]), "=r"(r[3]) : "r"(addr));
}
__device__ __forceinline__ void mma_tf32(float d[4], const unsigned a[4], const unsigned b[2]) {
    asm volatile(
        "mma.sync.aligned.m16n8k8.row.col.f32.tf32.tf32.f32 "
        "{%0,%1,%2,%3}, {%4,%5,%6,%7}, {%8,%9}, {%0,%1,%2,%3};\n"
        : "+f"(d[0]), "+f"(d[1]), "+f"(d[2]), "+f"(d[3])
        : "r"(a[0]), "r"(a[1]), "r"(a[2]), "r"(a[3]),
          "r"(b[0]), "r"(b[1]));
}
__device__ __forceinline__ uint32_t sw128(uint32_t off) { return off ^ ((off >> 3) & 0x70); }

// ---------------------------------------------------------------------------
// K_PREP fused grid:
//   [0, 1024)            xnorm (one batch row each)
//   [1024, 1024+128)     chain (warp-ballot fwd+bwd, 1 elem/warp)
//   [1152, 1152+6250)    winv  (2 class rows per warp, MLP=4)
// ---------------------------------------------------------------------------
__global__ void k_prep(const float* __restrict__ x, const int* __restrict__ tgt,
                       const float4* __restrict__ w4, float* __restrict__ out_t) {
    const int by = blockIdx.x;
    const int t = threadIdx.x;

    if (by < B_NUM) {                    // ---- xnorm row `by` ----
        __shared__ float ws[8];
        float v = x[by * D_NUM + t];
        float ss = v * v;
        #pragma unroll
        for (int o = 16; o; o >>= 1) ss += __shfl_xor_sync(0xffffffffu, ss, o);
        if ((t & 31) == 0) ws[t >> 5] = ss;
        __syncthreads();
        float tot = 0.f;
        #pragma unroll
        for (int i = 0; i < 8; ++i) tot += ws[i];
        float inv = 1.f / fmaxf(sqrtf(tot), EPSV);
        float xn = v * inv;
        g_xexact[by * D_NUM + t] = xn;
        g_xnorm[by * D_NUM + t] = __uint_as_float(f2tf(xn));
        if (t == 0) out_t[by] = (float)tgt[by];
    } else if (by < B_NUM + CHAIN_BLKS) {   // ---- chain: ballot scans ----
        __shared__ int st[B_NUM];
        #pragma unroll
        for (int k = 0; k < 4; ++k) st[t + k * 256] = tgt[t + k * 256];
        __syncthreads();
        const int lane = t & 31;
        const int i = (by - B_NUM) * 8 + (t >> 5);   // 0..1023, one per warp
        const int me = st[i];
        // closest predecessor (largest j < i with st[j]==me)
        int prev = -1;
        for (int start = i - 1; start >= 0; start -= 32) {
            int j = start - lane;
            unsigned m = __ballot_sync(0xffffffffu, (j >= 0) && (st[j] == me));
            if (m) { prev = start - (__ffs(m) - 1); break; }
        }
        // closest successor (smallest j > i with st[j]==me)
        int nxt = -1;
        for (int start = i + 1; start < B_NUM; start += 32) {
            int j = start + lane;
            unsigned m = __ballot_sync(0xffffffffu, (j < B_NUM) && (st[j] == me));
            if (m) { nxt = start + (__ffs(m) - 1); break; }
        }
        if (lane == 0) {
            g_head[i] = (prev < 0) ? 1 : 0;
            g_next[i] = nxt;
        }
    } else {                             // ---- winv: 2 class rows per warp ----
        int gw = ((by - B_NUM - CHAIN_BLKS) * 8 + (t >> 5)) * 2;
        int lane = t & 31;
        if (gw < C_NUM) {
            const float4* r0 = w4 + (size_t)gw * 64;
            const float4* r1 = w4 + (size_t)(gw + 1) * 64;
            float4 a0 = r0[lane];
            float4 b0 = r0[lane + 32];
            float4 a1 = r1[lane];
            float4 b1 = r1[lane + 32];
            float s0 = a0.x*a0.x + a0.y*a0.y + a0.z*a0.z + a0.w*a0.w
                     + b0.x*b0.x + b0.y*b0.y + b0.z*b0.z + b0.w*b0.w;
            float s1 = a1.x*a1.x + a1.y*a1.y + a1.z*a1.z + a1.w*a1.w
                     + b1.x*b1.x + b1.y*b1.y + b1.z*b1.z + b1.w*b1.w;
            #pragma unroll
            for (int o = 16; o; o >>= 1) {
                s0 += __shfl_xor_sync(0xffffffffu, s0, o);
                s1 += __shfl_xor_sync(0xffffffffu, s1, o);
            }
            if (lane == 0) {
                g_winv[gw] = 1.f / fmaxf(sqrtf(s0), EPSV);
                g_winv[gw + 1] = 1.f / fmaxf(sqrtf(s1), EPSV);
            }
        }
    }
}

// ---------------------------------------------------------------------------
// K_GEMM: TF32 mma.sync. 128x128 CTA tile, 8 warps @ 64x32, BK=32,
//         3-stage cp.async, single barrier/iter, leading copy CTAs. (R6 core)
// ---------------------------------------------------------------------------
#define NSTG 3
#define STG_BYTES 32768            // A(16KB) + B(16KB) per stage
#define OFF_TILE 1024
#define SMEM_BYTES (OFF_TILE + NSTG * STG_BYTES)

__global__ __launch_bounds__(256, 2)
void k_gemm(const float* __restrict__ W, float* __restrict__ out,
            float4* __restrict__ nw4) {
    const int tid = threadIdx.x;

    // ---- leading copy CTAs: W -> new_weight output region (overlaps GEMM) ----
    if (blockIdx.y < COPY_CTAS_Y) {
        const float4* src = (const float4*)W;
        const size_t n4 = (size_t)C_NUM * 64;
        const size_t nthr = (size_t)COPY_CTAS_Y * 8 * 256;   // 32768
        size_t base = (size_t)(blockIdx.y * 8 + blockIdx.x) * 256 + tid;
        size_t i = base;
        for (; i + 3 * nthr < n4; i += 4 * nthr) {
            float4 v0 = src[i];
            float4 v1 = src[i + nthr];
            float4 v2 = src[i + 2 * nthr];
            float4 v3 = src[i + 3 * nthr];
            nw4[i] = v0; nw4[i + nthr] = v1;
            nw4[i + 2 * nthr] = v2; nw4[i + 3 * nthr] = v3;
        }
        for (; i < n4; i += nthr) nw4[i] = src[i];
        return;
    }

    extern __shared__ char smem[];
    const uint32_t sb = smem_u32(smem);
    const int lane = tid & 31, warp = tid >> 5;
    const int b0 = blockIdx.x * 128;                    // batch tile
    const int c0 = (blockIdx.y - COPY_CTAS_Y) * 128;    // class tile
    const int wm = (warp & 1) * 64;
    const int wn = (warp >> 1) * 32;

    float* winv_s = (float*)smem;      // [128] = 30*winv
    if (tid < 128) {
        int c = c0 + tid; if (c >= C_NUM) c = C_NUM - 1;
        winv_s[tid] = 30.0f * g_winv[c];
    }

    const char* Abase = (const char*)g_xnorm + (size_t)b0 * (D_NUM * 4);
    const char* Bbase = (const char*)W;

    auto issue_load = [&](int stage, int chunk) {
        uint32_t abuf = sb + OFF_TILE + stage * STG_BYTES;
        uint32_t bbuf = abuf + 16384;
        #pragma unroll
        for (int i = 0; i < 4; ++i) {
            int slot = tid + i * 256;          // 0..1023
            int r = slot >> 3;
            int sg = (slot & 7) * 16;
            uint32_t so = sw128((uint32_t)(r * 128 + sg));
            cp16(abuf + so, Abase + (size_t)r * 1024 + chunk * 128 + sg);
            int row = c0 + r; if (row >= C_NUM) row = C_NUM - 1;
            cp16(bbuf + so, Bbase + (size_t)row * 1024 + chunk * 128 + sg);
        }
        CP_COMMIT();
    };

    float acc[4][4][4];
    #pragma unroll
    for (int i = 0; i < 4; ++i)
        #pragma unroll
        for (int j = 0; j < 4; ++j)
            #pragma unroll
            for (int r = 0; r < 4; ++r) acc[i][j][r] = 0.f;

    uint32_t a_off[4], b_off[2];
    #pragma unroll
    for (int im = 0; im < 4; ++im)
        a_off[im] = (uint32_t)((wm + im * 16 + (lane & 15)) * 128 + ((lane >> 4) << 4));
    #pragma unroll
    for (int jp = 0; jp < 2; ++jp)
        b_off[jp] = (uint32_t)((wn + jp * 16 + ((lane >> 4) << 3) + (lane & 7)) * 128
                               + (((lane >> 3) & 1) << 4));

    issue_load(0, 0);
    issue_load(1, 1);

    #pragma unroll
    for (int c = 0; c < 8; ++c) {
        if (c < 7) asm volatile("cp.async.wait_group 1;" ::: "memory");
        else       asm volatile("cp.async.wait_group 0;" ::: "memory");
        __syncthreads();
        if (c + 2 < 8) issue_load((c + 2) % NSTG, c + 2);  // stage freed at this barrier

        const uint32_t abuf = sb + OFF_TILE + (c % NSTG) * STG_BYTES;
        const uint32_t bbuf = abuf + 16384;
        #pragma unroll
        for (int ks = 0; ks < 4; ++ks) {
            unsigned af[4][4], bf[2][4];
            #pragma unroll
            for (int im = 0; im < 4; ++im)
                ldsm4(af[im], abuf + sw128(a_off[im] + ks * 32));
            #pragma unroll
            for (int jp = 0; jp < 2; ++jp)
                ldsm4(bf[jp], bbuf + sw128(b_off[jp] + ks * 32));
            #pragma unroll
            for (int im = 0; im < 4; ++im) {
                #pragma unroll
                for (int jp = 0; jp < 2; ++jp) {
                    mma_tf32(acc[im][jp * 2 + 0], af[im], &bf[jp][0]);
                    mma_tf32(acc[im][jp * 2 + 1], af[im], &bf[jp][2]);
                }
            }
        }
    }
    __syncthreads();   // all reads of last stage done before tb reuse

    // epilogue: scale by 30*winv, smem transpose, coalesced float4 stores
    float* tb = (float*)(smem + OFF_TILE);   // [128][132]
    const int g4 = lane >> 2, t4 = lane & 3;
    #pragma unroll
    for (int im = 0; im < 4; ++im) {
        int r = wm + im * 16 + g4;
        #pragma unroll
        for (int jn = 0; jn < 4; ++jn) {
            int col = wn + jn * 8 + t4 * 2;
            float s0 = winv_s[col], s1 = winv_s[col + 1];
            *(float2*)&tb[r * 132 + col] =
                make_float2(acc[im][jn][0] * s0, acc[im][jn][1] * s1);
            *(float2*)&tb[(r + 8) * 132 + col] =
                make_float2(acc[im][jn][2] * s0, acc[im][jn][3] * s1);
        }
    }
    __syncthreads();
    #pragma unroll
    for (int it = 0; it < 16; ++it) {
        int r = warp + it * 8;
        int colb = lane * 4;
        float4 val = *(const float4*)&tb[r * 132 + colb];
        int gc = c0 + colb;
        if (gc < C_NUM)
            *(float4*)&out[(size_t)(b0 + r) * C_NUM + gc] = val;
    }
}

// ---------------------------------------------------------------------------
// K_UPDATE: sequential momentum update per class chain (reads copied rows)
// ---------------------------------------------------------------------------
__global__ void k_update(const int* __restrict__ tgt, float* __restrict__ nw) {
    int b = blockIdx.x;
    if (!g_head[b]) return;
    int t = threadIdx.x;
    int y = tgt[b];
    float v = nw[(size_t)y * D_NUM + t];
    __shared__ float ws[8];
    int cur = b;
    while (cur >= 0) {
        v = 0.5f * v + 0.5f * g_xexact[cur * D_NUM + t];
        float ss = v * v;
        #pragma unroll
        for (int o = 16; o; o >>= 1) ss += __shfl_xor_sync(0xffffffffu, ss, o);
        __syncthreads();
        if ((t & 31) == 0) ws[t >> 5] = ss;
        __syncthreads();
        float tot = 0.f;
        #pragma unroll
        for (int i = 0; i < 8; ++i) tot += ws[i];
        v *= 1.f / fmaxf(sqrtf(tot), EPSV);
        cur = g_next[cur];
    }
    nw[(size_t)y * D_NUM + t] = v;
}

// ---------------------------------------------------------------------------
extern "C" void kernel_launch(void* const* d_in, const int* in_sizes, int n_in,
                              void* d_out, int out_size) {
    const float* x   = (const float*)d_in[0];
    const int*   tgt = (const int*)d_in[1];
    const float* w   = (const float*)d_in[2];
    float* out      = (float*)d_out;
    float* out_pred = out;                                  // [1024][100000]
    float* out_t    = out + (size_t)B_NUM * C_NUM;          // [1024]
    float* out_nw   = out_t + B_NUM;                        // [100000][256]

    static bool attr_set = false;
    if (!attr_set) {
        cudaFuncSetAttribute(k_gemm, cudaFuncAttributeMaxDynamicSharedMemorySize, SMEM_BYTES);
        attr_set = true;
    }

    k_prep<<<B_NUM + CHAIN_BLKS + WINV_BLKS, 256>>>(x, tgt, (const float4*)w, out_t);
    k_gemm<<<dim3(8, COPY_CTAS_Y + GEMM_TILES_Y), 256, SMEM_BYTES>>>(w, out_pred, (float4*)out_nw);
    k_update<<<B_NUM, 256>>>(tgt, out_nw);
}